// round 5
// baseline (speedup 1.0000x reference)
#include <cuda_runtime.h>
#include <math.h>
#include <stdint.h>

// Problem constants
#define NUC 80000
#define NPC 40000
#define NEC 160000
#define DMC 256
#define NHC 4
#define NDC 64
#define LDPROJ 768

static const size_t SZ_U = (size_t)NUC * DMC;
static const size_t SZ_P = (size_t)NPC * DMC;

// Scratch layout (floats)
static const size_t OFF_XUA   = 0;
static const size_t OFF_XUB   = SZ_U;
static const size_t OFF_PROJU = 2 * SZ_U;                    // NU*768
static const size_t OFF_AGGU  = 5 * SZ_U;
static const size_t OFF_XPB   = 6 * SZ_U;
static const size_t OFF_PROJP = OFF_XPB + SZ_P;              // NP*768
static const size_t OFF_AGGP  = OFF_XPB + 4 * SZ_P;
static const size_t OFF_WBIG  = OFF_XPB + 5 * SZ_P;          // 4 * 256*768
static const size_t OFF_BBIG  = OFF_WBIG + (size_t)4 * DMC * LDPROJ;
static const size_t OFF_INT   = OFF_BBIG + 4 * LDPROJ;
static const size_t I_ROWP = 0;
static const size_t I_ROWU = I_ROWP + NPC + 1;
static const size_t I_DEGP = I_ROWU + NUC + 1;
static const size_t I_DEGU = I_DEGP + NPC;
static const size_t I_CURP = I_DEGU + NUC;
static const size_t I_CURU = I_CURP + NPC;
static const size_t I_COLP = I_CURU + NUC;
static const size_t I_COLU = I_COLP + NEC;
static const size_t N_INTS = I_COLU + NEC;
static const size_t TOTAL_F = OFF_INT + N_INTS;

__device__ float g_buf[TOTAL_F];

// ---------------------------------------------------------------------------
__device__ __forceinline__ float gelu_f(float x) {
    return 0.5f * x * (1.0f + erff(x * 0.70710678118654752f));
}

__device__ __forceinline__ uint32_t f2tf(float f) {
    uint32_t u;
    asm("cvt.rna.tf32.f32 %0, %1;" : "=r"(u) : "f"(f));
    return u;
}

// ---------------------------------------------------------------------------
// Assemble Wbig[c][256][768] = [ Wq | Wk@arel | Wv@mrel ]  (c = l*2 + t)
__global__ void copyq_kernel(const float* __restrict__ Wq, const float* __restrict__ bq,
                             float* __restrict__ Wbig, float* __restrict__ bbig) {
    int c = blockIdx.x, i = blockIdx.y, j = threadIdx.x;
    Wbig[(size_t)c * DMC * LDPROJ + (size_t)i * LDPROJ + j] = Wq[(size_t)c * DMC * DMC + (size_t)i * DMC + j];
    if (i == 0) bbig[(size_t)c * LDPROJ + j] = bq[(size_t)c * DMC + j];
}

__global__ void fuse_w_kernel(const float* __restrict__ Wk, const float* __restrict__ Wv,
                              const float* __restrict__ arel, const float* __restrict__ mrel,
                              float* __restrict__ Wbig) {
    int c = blockIdx.x, i = blockIdx.y, j = threadIdx.x;
    int kv = c >> 2;
    int lt = c & 3;
    const float* Wsrc = (kv ? Wv : Wk) + (size_t)lt * DMC * DMC;
    const float* R    = (kv ? mrel : arel) + (size_t)lt * NHC * NDC * NDC;
    int h = j >> 6, e = j & 63;
    const float* wrow = Wsrc + (size_t)i * DMC + h * NDC;
    const float* rr   = R + (size_t)h * NDC * NDC + e;
    float sum = 0.0f;
#pragma unroll 8
    for (int d = 0; d < NDC; d++) sum = fmaf(wrow[d], rr[(size_t)d * NDC], sum);
    Wbig[(size_t)lt * DMC * LDPROJ + (size_t)i * LDPROJ + DMC + kv * DMC + j] = sum;
}

__global__ void fuse_b_kernel(const float* __restrict__ bk, const float* __restrict__ bv,
                              const float* __restrict__ arel, const float* __restrict__ mrel,
                              float* __restrict__ bbig) {
    int c = blockIdx.x, j = threadIdx.x;
    int kv = c >> 2;
    int lt = c & 3;
    const float* bsrc = (kv ? bv : bk) + (size_t)lt * DMC;
    const float* R    = (kv ? mrel : arel) + (size_t)lt * NHC * NDC * NDC;
    int h = j >> 6, e = j & 63;
    float sum = 0.0f;
#pragma unroll 8
    for (int d = 0; d < NDC; d++)
        sum = fmaf(bsrc[h * NDC + d], R[(size_t)h * NDC * NDC + (size_t)d * NDC + e], sum);
    bbig[(size_t)lt * LDPROJ + DMC + kv * DMC + j] = sum;
}

// ---------------------------------------------------------------------------
__global__ void gather_kernel(const int* __restrict__ ids, const float* __restrict__ tab,
                              float* __restrict__ out) {
    size_t i = (size_t)blockIdx.x * blockDim.x + threadIdx.x;
    if (i >= (size_t)NUC * (DMC / 4)) return;
    size_t row = i >> 6;
    int c4 = (int)(i & 63);
    ((float4*)out)[i] = ((const float4*)(tab + (size_t)ids[row] * DMC))[c4];
}

// ---------------------------------------------------------------------------
// CSR construction
__global__ void count_deg(const int* __restrict__ src, const int* __restrict__ dst,
                          int* __restrict__ degP, int* __restrict__ degU) {
    int e = blockIdx.x * blockDim.x + threadIdx.x;
    if (e >= NEC) return;
    atomicAdd(&degP[dst[e]], 1);
    atomicAdd(&degU[src[e]], 1);
}

__global__ __launch_bounds__(1024)
void scan_kernel(const int* __restrict__ deg, int* __restrict__ rowptr,
                 int* __restrict__ cursor, int n) {
    __shared__ int wsums[32];
    int t = threadIdx.x;
    int lane = t & 31, wid = t >> 5;
    int C = (n + 1023) / 1024;
    int start = t * C; if (start > n) start = n;
    int end = start + C; if (end > n) end = n;
    int s = 0;
    for (int i = start; i < end; i++) s += deg[i];
    int v = s;
#pragma unroll
    for (int o = 1; o < 32; o <<= 1) {
        int u = __shfl_up_sync(0xffffffffu, v, o);
        if (lane >= o) v += u;
    }
    if (lane == 31) wsums[wid] = v;
    __syncthreads();
    if (wid == 0) {
        int wv = wsums[lane];
#pragma unroll
        for (int o = 1; o < 32; o <<= 1) {
            int u = __shfl_up_sync(0xffffffffu, wv, o);
            if (lane >= o) wv += u;
        }
        wsums[lane] = wv;
    }
    __syncthreads();
    int warp_off = (wid > 0) ? wsums[wid - 1] : 0;
    int run = warp_off + v - s;
    for (int i = start; i < end; i++) {
        rowptr[i] = run;
        cursor[i] = run;
        run += deg[i];
    }
    if (t == 0) rowptr[n] = wsums[31];
}

__global__ void build_csr(const int* __restrict__ src, const int* __restrict__ dst,
                          int* __restrict__ curP, int* __restrict__ curU,
                          int* __restrict__ colP, int* __restrict__ colU) {
    int e = blockIdx.x * blockDim.x + threadIdx.x;
    if (e >= NEC) return;
    int s = src[e], d = dst[e];
    colP[atomicAdd(&curP[d], 1)] = s;
    colU[atomicAdd(&curU[s], 1)] = d;
}

// ---------------------------------------------------------------------------
// TF32 tensor-core GEMM with software-pipelined global loads.
__global__ __launch_bounds__(256)
void gemm_tf32(const float* __restrict__ A, int lda,
               const float* __restrict__ W, int ldw,
               const float* __restrict__ bias,
               float* __restrict__ C, int ldc,
               int mode, const float* __restrict__ xold,
               const float* __restrict__ skipPtr, int gelu_after) {
    __shared__ uint32_t As[64][20];
    __shared__ uint32_t Bs[16][136];

    const int bm = blockIdx.y * 64;
    const int bn = blockIdx.x * 128;
    const int t  = threadIdx.x;
    const int warp = t >> 5;
    const int lane = t & 31;
    const int wm = warp >> 2;
    const int wn = warp & 3;
    const int lr = lane >> 2;
    const int lc = lane & 3;

    const int ga_r = t >> 2;
    const int ga_c = (t & 3) << 2;
    const int gb_k = t >> 5;
    const int gb_c = (t & 31) << 2;

    const float* Aptr = A + (size_t)(bm + ga_r) * lda + ga_c;
    const float* Wptr0 = W + (size_t)gb_k * ldw + bn + gb_c;
    const float* Wptr1 = W + (size_t)(gb_k + 8) * ldw + bn + gb_c;

    float c[2][4][4];
#pragma unroll
    for (int mi = 0; mi < 2; mi++)
#pragma unroll
        for (int ni = 0; ni < 4; ni++)
#pragma unroll
            for (int r = 0; r < 4; r++) c[mi][ni][r] = 0.0f;

    // prefetch first tiles
    float4 av = *(const float4*)(Aptr);
    float4 w0 = *(const float4*)(Wptr0);
    float4 w1 = *(const float4*)(Wptr1);

    for (int k0 = 0; k0 < 256; k0 += 16) {
        // commit prefetched tile to smem
        As[ga_r][ga_c + 0] = f2tf(av.x);
        As[ga_r][ga_c + 1] = f2tf(av.y);
        As[ga_r][ga_c + 2] = f2tf(av.z);
        As[ga_r][ga_c + 3] = f2tf(av.w);
        Bs[gb_k][gb_c + 0] = f2tf(w0.x);
        Bs[gb_k][gb_c + 1] = f2tf(w0.y);
        Bs[gb_k][gb_c + 2] = f2tf(w0.z);
        Bs[gb_k][gb_c + 3] = f2tf(w0.w);
        Bs[gb_k + 8][gb_c + 0] = f2tf(w1.x);
        Bs[gb_k + 8][gb_c + 1] = f2tf(w1.y);
        Bs[gb_k + 8][gb_c + 2] = f2tf(w1.z);
        Bs[gb_k + 8][gb_c + 3] = f2tf(w1.w);
        __syncthreads();

        // prefetch next tile (overlaps with MMA compute below)
        if (k0 + 16 < 256) {
            av = *(const float4*)(Aptr + k0 + 16);
            w0 = *(const float4*)(Wptr0 + (size_t)(k0 + 16) * ldw);
            w1 = *(const float4*)(Wptr1 + (size_t)(k0 + 16) * ldw);
        }

#pragma unroll
        for (int ks = 0; ks < 2; ks++) {
            const int kb = ks << 3;
            uint32_t a[2][4], b[4][2];
#pragma unroll
            for (int mi = 0; mi < 2; mi++) {
                int row = wm * 32 + mi * 16 + lr;
                a[mi][0] = As[row][kb + lc];
                a[mi][1] = As[row + 8][kb + lc];
                a[mi][2] = As[row][kb + lc + 4];
                a[mi][3] = As[row + 8][kb + lc + 4];
            }
#pragma unroll
            for (int ni = 0; ni < 4; ni++) {
                int col = wn * 32 + ni * 8 + lr;
                b[ni][0] = Bs[kb + lc][col];
                b[ni][1] = Bs[kb + lc + 4][col];
            }
#pragma unroll
            for (int mi = 0; mi < 2; mi++)
#pragma unroll
                for (int ni = 0; ni < 4; ni++) {
                    asm volatile(
                        "mma.sync.aligned.m16n8k8.row.col.f32.tf32.tf32.f32 "
                        "{%0,%1,%2,%3}, {%4,%5,%6,%7}, {%8,%9}, {%0,%1,%2,%3};"
                        : "+f"(c[mi][ni][0]), "+f"(c[mi][ni][1]),
                          "+f"(c[mi][ni][2]), "+f"(c[mi][ni][3])
                        : "r"(a[mi][0]), "r"(a[mi][1]), "r"(a[mi][2]), "r"(a[mi][3]),
                          "r"(b[ni][0]), "r"(b[ni][1]));
                }
        }
        __syncthreads();
    }

    float beta = 1.0f, omb = 0.0f;
    if (mode == 1) {
        float sv = *skipPtr;
        beta = 1.0f / (1.0f + expf(-sv));
        omb = 1.0f - beta;
    }

#pragma unroll
    for (int mi = 0; mi < 2; mi++) {
#pragma unroll
        for (int ni = 0; ni < 4; ni++) {
            int row0 = bm + wm * 32 + mi * 16 + lr;
            int col  = bn + wn * 32 + ni * 8 + (lc << 1);
            float b0 = bias[col], b1 = bias[col + 1];
#pragma unroll
            for (int half = 0; half < 2; half++) {
                int row = row0 + half * 8;
                float v0 = c[mi][ni][half * 2 + 0] + b0;
                float v1 = c[mi][ni][half * 2 + 1] + b1;
                if (mode == 1) {
                    float2 xo = *(const float2*)(xold + (size_t)row * DMC + col);
                    v0 = beta * v0 + omb * xo.x;
                    v1 = beta * v1 + omb * xo.y;
                }
                if (gelu_after) { v0 = gelu_f(v0); v1 = gelu_f(v1); }
                *(float2*)(C + (size_t)row * ldc + col) = make_float2(v0, v1);
            }
        }
    }
}

// ---------------------------------------------------------------------------
// Fused edge attention + aggregation + GELU, 2-way unrolled neighbor loops.
__global__ __launch_bounds__(256)
void agg_kernel(const int* __restrict__ rowptr, const int* __restrict__ col,
                const float* __restrict__ q, const float* __restrict__ kt,
                const float* __restrict__ vt, const float* __restrict__ prel,
                float* __restrict__ agg, int ndst) {
    int gid = blockIdx.x * blockDim.x + threadIdx.x;
    int w = gid >> 5;
    int lane = gid & 31;
    if (w >= ndst * NHC) return;
    int dN = w >> 2;
    int h = w & 3;
    int base = rowptr[dN];
    int deg = rowptr[dN + 1] - base;

    float accx = 0.0f, accy = 0.0f;
    if (deg > 0) {
        const size_t hoff = (size_t)h * NDC + lane * 2;
        float2 qv = *(const float2*)(q + (size_t)dN * LDPROJ + hoff);
        float pr = prel[h] * 0.125f;

        if (deg <= 32) {
            float lg0 = -INFINITY;
            float m = -INFINITY;
            int j = 0;
            for (; j + 1 < deg; j += 2) {
                int s0 = col[base + j];
                int s1 = col[base + j + 1];
                float2 k0 = *(const float2*)(kt + (size_t)s0 * LDPROJ + hoff);
                float2 k1 = *(const float2*)(kt + (size_t)s1 * LDPROJ + hoff);
                float p0 = qv.x * k0.x + qv.y * k0.y;
                float p1 = qv.x * k1.x + qv.y * k1.y;
#pragma unroll
                for (int o = 16; o > 0; o >>= 1) {
                    p0 += __shfl_xor_sync(0xffffffffu, p0, o);
                    p1 += __shfl_xor_sync(0xffffffffu, p1, o);
                }
                float l0 = p0 * pr, l1 = p1 * pr;
                if (j == lane)     lg0 = l0;
                if (j + 1 == lane) lg0 = l1;
                m = fmaxf(m, fmaxf(l0, l1));
            }
            if (j < deg) {
                int s0 = col[base + j];
                float2 k0 = *(const float2*)(kt + (size_t)s0 * LDPROJ + hoff);
                float p0 = qv.x * k0.x + qv.y * k0.y;
#pragma unroll
                for (int o = 16; o > 0; o >>= 1) p0 += __shfl_xor_sync(0xffffffffu, p0, o);
                float l0 = p0 * pr;
                if (j == lane) lg0 = l0;
                m = fmaxf(m, l0);
            }
            float e0 = (lane < deg) ? expf(lg0 - m) : 0.0f;
            float tsum = e0;
#pragma unroll
            for (int o = 16; o > 0; o >>= 1) tsum += __shfl_xor_sync(0xffffffffu, tsum, o);
            float inv = 1.0f / (tsum + 1e-16f);
            j = 0;
            for (; j + 1 < deg; j += 2) {
                float a0 = __shfl_sync(0xffffffffu, e0, j) * inv;
                float a1 = __shfl_sync(0xffffffffu, e0, j + 1) * inv;
                int s0 = col[base + j];
                int s1 = col[base + j + 1];
                float2 v0 = *(const float2*)(vt + (size_t)s0 * LDPROJ + hoff);
                float2 v1 = *(const float2*)(vt + (size_t)s1 * LDPROJ + hoff);
                accx = fmaf(a0, v0.x, accx);
                accy = fmaf(a0, v0.y, accy);
                accx = fmaf(a1, v1.x, accx);
                accy = fmaf(a1, v1.y, accy);
            }
            if (j < deg) {
                float a0 = __shfl_sync(0xffffffffu, e0, j) * inv;
                int s0 = col[base + j];
                float2 v0 = *(const float2*)(vt + (size_t)s0 * LDPROJ + hoff);
                accx = fmaf(a0, v0.x, accx);
                accy = fmaf(a0, v0.y, accy);
            }
        } else {
            // recompute path (rare; any degree)
            float m = -INFINITY;
            for (int j = 0; j < deg; j++) {
                int s = col[base + j];
                float2 kv = *(const float2*)(kt + (size_t)s * LDPROJ + hoff);
                float p = qv.x * kv.x + qv.y * kv.y;
#pragma unroll
                for (int o = 16; o > 0; o >>= 1) p += __shfl_xor_sync(0xffffffffu, p, o);
                m = fmaxf(m, p * pr);
            }
            float ssum = 0.0f;
            for (int j = 0; j < deg; j++) {
                int s = col[base + j];
                float2 kv = *(const float2*)(kt + (size_t)s * LDPROJ + hoff);
                float p = qv.x * kv.x + qv.y * kv.y;
#pragma unroll
                for (int o = 16; o > 0; o >>= 1) p += __shfl_xor_sync(0xffffffffu, p, o);
                ssum += expf(p * pr - m);
            }
            float inv = 1.0f / (ssum + 1e-16f);
            for (int j = 0; j < deg; j++) {
                int s = col[base + j];
                float2 kv = *(const float2*)(kt + (size_t)s * LDPROJ + hoff);
                float p = qv.x * kv.x + qv.y * kv.y;
#pragma unroll
                for (int o = 16; o > 0; o >>= 1) p += __shfl_xor_sync(0xffffffffu, p, o);
                float a = expf(p * pr - m) * inv;
                float2 v = *(const float2*)(vt + (size_t)s * LDPROJ + hoff);
                accx = fmaf(a, v.x, accx);
                accy = fmaf(a, v.y, accy);
            }
        }
    }
    *(float2*)(agg + (size_t)dN * DMC + (size_t)h * NDC + lane * 2) =
        make_float2(gelu_f(accx), gelu_f(accy));
}

// ---------------------------------------------------------------------------
extern "C" void kernel_launch(void* const* d_in, const int* in_sizes, int n_in,
                              void* d_out, int out_size) {
    (void)in_sizes; (void)n_in; (void)out_size;

    float* base = nullptr;
    cudaGetSymbolAddress((void**)&base, g_buf);

    const int*   user_ids  = (const int*)d_in[0];
    const float* x_product = (const float*)d_in[1];
    const int*   edge_src  = (const int*)d_in[2];
    const int*   edge_dst  = (const int*)d_in[3];
    const float* emb       = (const float*)d_in[4];
    const float* Wk        = (const float*)d_in[5];
    const float* bk        = (const float*)d_in[6];
    const float* Wq        = (const float*)d_in[7];
    const float* bq        = (const float*)d_in[8];
    const float* Wv        = (const float*)d_in[9];
    const float* bv        = (const float*)d_in[10];
    const float* Wout      = (const float*)d_in[11];
    const float* bout      = (const float*)d_in[12];
    const float* skipp     = (const float*)d_in[13];
    const float* arel      = (const float*)d_in[14];
    const float* mrel      = (const float*)d_in[15];
    const float* prel      = (const float*)d_in[16];

    float* xuA   = base + OFF_XUA;
    float* xuB   = base + OFF_XUB;
    float* projU = base + OFF_PROJU;
    float* aggU  = base + OFF_AGGU;
    float* xpB   = base + OFF_XPB;
    float* projP = base + OFF_PROJP;
    float* aggP  = base + OFF_AGGP;
    float* Wbig  = base + OFF_WBIG;
    float* bbig  = base + OFF_BBIG;

    int* ibase   = (int*)(base + OFF_INT);
    int* rowptrP = ibase + I_ROWP;
    int* rowptrU = ibase + I_ROWU;
    int* degP    = ibase + I_DEGP;
    int* degU    = ibase + I_DEGU;
    int* curP    = ibase + I_CURP;
    int* curU    = ibase + I_CURU;
    int* colP    = ibase + I_COLP;
    int* colU    = ibase + I_COLU;

    float* out_xu = (float*)d_out;
    float* out_xp = (float*)d_out + SZ_U;

    // 1. Fused projection weights
    copyq_kernel<<<dim3(4, 256), 256>>>(Wq, bq, Wbig, bbig);
    fuse_w_kernel<<<dim3(8, 256), 256>>>(Wk, Wv, arel, mrel, Wbig);
    fuse_b_kernel<<<8, 256>>>(bk, bv, arel, mrel, bbig);

    // 2. Gather user embeddings
    {
        size_t n = (size_t)NUC * (DMC / 4);
        gather_kernel<<<(unsigned)((n + 255) / 256), 256>>>(user_ids, emb, xuA);
    }

    // 3. Build CSRs (both directions), reused across layers
    cudaMemsetAsync(degP, 0, (size_t)NPC * sizeof(int));
    cudaMemsetAsync(degU, 0, (size_t)NUC * sizeof(int));
    count_deg<<<(NEC + 255) / 256, 256>>>(edge_src, edge_dst, degP, degU);
    scan_kernel<<<1, 1024>>>(degP, rowptrP, curP, NPC);
    scan_kernel<<<1, 1024>>>(degU, rowptrU, curU, NUC);
    build_csr<<<(NEC + 255) / 256, 256>>>(edge_src, edge_dst, curP, curU, colP, colU);

    for (int l = 0; l < 2; l++) {
        const float* xu_in = l ? xuB : xuA;
        const float* xp_in = l ? xpB : x_product;
        float* xu_out = l ? out_xu : xuB;
        float* xp_out = l ? out_xp : xpB;
        int gelu_after = (l == 0) ? 1 : 0;

        // Projections: one [M,256]x[256,768] GEMM per node type
        {
            size_t cu = (size_t)(l * 2 + 0), cp = (size_t)(l * 2 + 1);
            gemm_tf32<<<dim3(6, NUC / 64), 256>>>(
                xu_in, DMC, Wbig + cu * DMC * LDPROJ, LDPROJ, bbig + cu * LDPROJ,
                projU, LDPROJ, 0, nullptr, nullptr, 0);
            gemm_tf32<<<dim3(6, NPC / 64), 256>>>(
                xp_in, DMC, Wbig + cp * DMC * LDPROJ, LDPROJ, bbig + cp * LDPROJ,
                projP, LDPROJ, 0, nullptr, nullptr, 0);
        }

        // rel 0: user -> product (dst = product)
        {
            unsigned blocks = (unsigned)(((size_t)NPC * NHC * 32 + 255) / 256);
            agg_kernel<<<blocks, 256>>>(rowptrP, colP,
                                        projP /*q*/, projU + DMC /*kt*/, projU + 2 * DMC /*vt*/,
                                        prel + (size_t)(l * 2 + 0) * NHC, aggP, NPC);
        }
        // rel 1: product -> user (dst = user)
        {
            unsigned blocks = (unsigned)(((size_t)NUC * NHC * 32 + 255) / 256);
            agg_kernel<<<blocks, 256>>>(rowptrU, colU,
                                        projU /*q*/, projP + DMC /*kt*/, projP + 2 * DMC /*vt*/,
                                        prel + (size_t)(l * 2 + 1) * NHC, aggU, NUC);
        }

        // Output GEMMs with skip blend (+ inter-layer gelu fused for l==0)
        {
            gemm_tf32<<<dim3(2, NPC / 64), 256>>>(
                aggP, DMC, Wout + (size_t)(l * 2 + 1) * DMC * DMC, DMC,
                bout + (size_t)(l * 2 + 1) * DMC, xp_out, DMC,
                1, xp_in, skipp + (l * 2 + 1), gelu_after);
            gemm_tf32<<<dim3(2, NUC / 64), 256>>>(
                aggU, DMC, Wout + (size_t)(l * 2 + 0) * DMC * DMC, DMC,
                bout + (size_t)(l * 2 + 0) * DMC, xu_out, DMC,
                1, xu_in, skipp + (l * 2 + 0), gelu_after);
        }
    }
}

// round 8
// speedup vs baseline: 1.1596x; 1.1596x over previous
#include <cuda_runtime.h>
#include <cuda_fp16.h>
#include <math.h>
#include <stdint.h>

#define NUC 80000
#define NPC 40000
#define NEC 160000
#define DMC 256
#define NHC 4
#define NDC 64
#define LDPROJ 768

static const size_t SZ_U = (size_t)NUC * DMC;
static const size_t SZ_P = (size_t)NPC * DMC;

// Scratch layout (floats)
static const size_t OFF_XUA   = 0;
static const size_t OFF_XUB   = SZ_U;
static const size_t OFF_PROJU = 2 * SZ_U;                      // NU*768 (3*SZ_U)
static const size_t OFF_AGGU  = 5 * SZ_U;
static const size_t OFF_XPB   = 6 * SZ_U;
static const size_t OFF_PROJP = OFF_XPB + SZ_P;                // NP*768 (3*SZ_P)
static const size_t OFF_AGGP  = OFF_XPB + 4 * SZ_P;
static const size_t OFF_WBIGT = OFF_XPB + 5 * SZ_P;            // fp16 [4][768][256] = 393216 floats
static const size_t OFF_BBIG  = OFF_WBIGT + (size_t)4 * LDPROJ * DMC / 2;
static const size_t OFF_WOUTT = OFF_BBIG + 4 * LDPROJ;         // fp16 [4][256][256] = 131072 floats
static const size_t OFF_INT   = OFF_WOUTT + (size_t)4 * DMC * DMC / 2;
static const size_t I_ROWP = 0;
static const size_t I_ROWU = I_ROWP + NPC + 1;
static const size_t I_DEGP = I_ROWU + NUC + 1;
static const size_t I_DEGU = I_DEGP + NPC;
static const size_t I_CURP = I_DEGU + NUC;
static const size_t I_CURU = I_CURP + NPC;
static const size_t I_COLP = I_CURU + NUC;
static const size_t I_COLU = I_COLP + NEC;
static const size_t N_INTS = I_COLU + NEC;
static const size_t TOTAL_F = OFF_INT + N_INTS;

__device__ float g_buf[TOTAL_F];

// ---------------------------------------------------------------------------
__device__ __forceinline__ float gelu_f(float x) {
    return 0.5f * x * (1.0f + erff(x * 0.70710678118654752f));
}

// ---------------------------------------------------------------------------
// Weight assembly: WbigT16[c][n][k] (fp16, transposed) = [Wq | Wk@arel | Wv@mrel]^T
__global__ void copyq_kernel(const float* __restrict__ Wq, const float* __restrict__ bq,
                             __half* __restrict__ WbigT, float* __restrict__ bbig) {
    int c = blockIdx.x, i = blockIdx.y, j = threadIdx.x;   // i = k, j = n
    WbigT[((size_t)c * LDPROJ + j) * DMC + i] =
        __float2half_rn(Wq[(size_t)c * DMC * DMC + (size_t)i * DMC + j]);
    if (i == 0) bbig[(size_t)c * LDPROJ + j] = bq[(size_t)c * DMC + j];
}

__global__ void fuse_w_kernel(const float* __restrict__ Wk, const float* __restrict__ Wv,
                              const float* __restrict__ arel, const float* __restrict__ mrel,
                              __half* __restrict__ WbigT) {
    int c = blockIdx.x, i = blockIdx.y, j = threadIdx.x;
    int kv = c >> 2, lt = c & 3;
    const float* Wsrc = (kv ? Wv : Wk) + (size_t)lt * DMC * DMC;
    const float* R    = (kv ? mrel : arel) + (size_t)lt * NHC * NDC * NDC;
    int h = j >> 6, e = j & 63;
    const float* wrow = Wsrc + (size_t)i * DMC + h * NDC;
    const float* rr   = R + (size_t)h * NDC * NDC + e;
    float sum = 0.0f;
#pragma unroll 8
    for (int d = 0; d < NDC; d++) sum = fmaf(wrow[d], rr[(size_t)d * NDC], sum);
    int n = DMC + kv * DMC + j;
    WbigT[((size_t)lt * LDPROJ + n) * DMC + i] = __float2half_rn(sum);
}

__global__ void fuse_b_kernel(const float* __restrict__ bk, const float* __restrict__ bv,
                              const float* __restrict__ arel, const float* __restrict__ mrel,
                              float* __restrict__ bbig) {
    int c = blockIdx.x, j = threadIdx.x;
    int kv = c >> 2, lt = c & 3;
    const float* bsrc = (kv ? bv : bk) + (size_t)lt * DMC;
    const float* R    = (kv ? mrel : arel) + (size_t)lt * NHC * NDC * NDC;
    int h = j >> 6, e = j & 63;
    float sum = 0.0f;
#pragma unroll 8
    for (int d = 0; d < NDC; d++)
        sum = fmaf(bsrc[h * NDC + d], R[(size_t)h * NDC * NDC + (size_t)d * NDC + e], sum);
    bbig[(size_t)lt * LDPROJ + DMC + kv * DMC + j] = sum;
}

__global__ void woutT_kernel(const float* __restrict__ Wout, __half* __restrict__ WoutT) {
    int c = blockIdx.x, k = blockIdx.y, n = threadIdx.x;
    WoutT[((size_t)c * DMC + n) * DMC + k] =
        __float2half_rn(Wout[(size_t)c * DMC * DMC + (size_t)k * DMC + n]);
}

// ---------------------------------------------------------------------------
__global__ void gather_kernel(const int* __restrict__ ids, const float* __restrict__ tab,
                              float* __restrict__ out) {
    size_t i = (size_t)blockIdx.x * blockDim.x + threadIdx.x;
    if (i >= (size_t)NUC * (DMC / 4)) return;
    size_t row = i >> 6;
    int c4 = (int)(i & 63);
    ((float4*)out)[i] = ((const float4*)(tab + (size_t)ids[row] * DMC))[c4];
}

// ---------------------------------------------------------------------------
// CSR construction
__global__ void count_deg(const int* __restrict__ src, const int* __restrict__ dst,
                          int* __restrict__ degP, int* __restrict__ degU) {
    int e = blockIdx.x * blockDim.x + threadIdx.x;
    if (e >= NEC) return;
    atomicAdd(&degP[dst[e]], 1);
    atomicAdd(&degU[src[e]], 1);
}

__global__ __launch_bounds__(1024)
void scan_kernel(const int* __restrict__ deg, int* __restrict__ rowptr,
                 int* __restrict__ cursor, int n) {
    __shared__ int wsums[32];
    int t = threadIdx.x;
    int lane = t & 31, wid = t >> 5;
    int C = (n + 1023) / 1024;
    int start = t * C; if (start > n) start = n;
    int end = start + C; if (end > n) end = n;
    int s = 0;
    for (int i = start; i < end; i++) s += deg[i];
    int v = s;
#pragma unroll
    for (int o = 1; o < 32; o <<= 1) {
        int u = __shfl_up_sync(0xffffffffu, v, o);
        if (lane >= o) v += u;
    }
    if (lane == 31) wsums[wid] = v;
    __syncthreads();
    if (wid == 0) {
        int wv = wsums[lane];
#pragma unroll
        for (int o = 1; o < 32; o <<= 1) {
            int u = __shfl_up_sync(0xffffffffu, wv, o);
            if (lane >= o) wv += u;
        }
        wsums[lane] = wv;
    }
    __syncthreads();
    int warp_off = (wid > 0) ? wsums[wid - 1] : 0;
    int run = warp_off + v - s;
    for (int i = start; i < end; i++) {
        rowptr[i] = run;
        cursor[i] = run;
        run += deg[i];
    }
    if (t == 0) rowptr[n] = wsums[31];
}

__global__ void build_csr(const int* __restrict__ src, const int* __restrict__ dst,
                          int* __restrict__ curP, int* __restrict__ curU,
                          int* __restrict__ colP, int* __restrict__ colU) {
    int e = blockIdx.x * blockDim.x + threadIdx.x;
    if (e >= NEC) return;
    int s = src[e], d = dst[e];
    colP[atomicAdd(&curP[d], 1)] = s;
    colU[atomicAdd(&curU[s], 1)] = d;
}

// ---------------------------------------------------------------------------
// FP16 tensor-core GEMM: C[M,N] = A[M,256] @ BT^T + bias.
// A fp32 row-major; BT fp16 row-major [N][256] (k contiguous). K=256, BK=32.
// Block tile 64(M) x 128(N), 256 threads, warp tile 32x32, m16n8k16.
__global__ __launch_bounds__(256)
void gemm_fp16(const float* __restrict__ A,
               const __half* __restrict__ BT,
               const float* __restrict__ bias,
               float* __restrict__ C, int ldc,
               int mode, const float* __restrict__ xold,
               const float* __restrict__ skipPtr, int gelu_after) {
    __shared__ __half As[64][40];    // stride 40 halves: conflict-free fragment loads
    __shared__ __half Bs[128][40];

    const int bm = blockIdx.y * 64;
    const int bn = blockIdx.x * 128;
    const int t  = threadIdx.x;
    const int warp = t >> 5;
    const int lane = t & 31;
    const int wm = warp >> 2;          // 0..1
    const int wn = warp & 3;           // 0..3
    const int lr = lane >> 2;          // 0..7
    const int lc = lane & 3;           // 0..3

    // loaders: A: 4 threads/row, 8 floats each; B: 2 threads/row, 16 halves each
    const int ar = t >> 2, ac = (t & 3) << 3;
    const int br = t >> 1, bc = (t & 1) << 4;
    const float* Aptr = A + (size_t)(bm + ar) * DMC + ac;
    const __half* Bptr = BT + (size_t)(bn + br) * DMC + bc;

    float acc[2][4][4];
#pragma unroll
    for (int mi = 0; mi < 2; mi++)
#pragma unroll
        for (int ni = 0; ni < 4; ni++)
#pragma unroll
            for (int r = 0; r < 4; r++) acc[mi][ni][r] = 0.0f;

    for (int k0 = 0; k0 < 256; k0 += 32) {
        // A tile 64x32 (fp32 -> fp16)
        {
            float4 f0 = *(const float4*)(Aptr + k0);
            float4 f1 = *(const float4*)(Aptr + k0 + 4);
            __half2* dsta = (__half2*)&As[ar][ac];
            dsta[0] = __floats2half2_rn(f0.x, f0.y);
            dsta[1] = __floats2half2_rn(f0.z, f0.w);
            dsta[2] = __floats2half2_rn(f1.x, f1.y);
            dsta[3] = __floats2half2_rn(f1.z, f1.w);
        }
        // B tile 128x32 (fp16 direct)
        {
            uint4 u0 = *(const uint4*)(Bptr + k0);
            uint4 u1 = *(const uint4*)(Bptr + k0 + 8);
            *(uint4*)&Bs[br][bc + 0] = u0;
            *(uint4*)&Bs[br][bc + 8] = u1;
        }
        __syncthreads();

#pragma unroll
        for (int ks = 0; ks < 2; ks++) {
            const int kb = ks << 4;
            uint32_t a[2][4], b[4][2];
#pragma unroll
            for (int mi = 0; mi < 2; mi++) {
                int row = wm * 32 + mi * 16 + lr;
                a[mi][0] = *(const uint32_t*)&As[row][kb + lc * 2];
                a[mi][1] = *(const uint32_t*)&As[row + 8][kb + lc * 2];
                a[mi][2] = *(const uint32_t*)&As[row][kb + lc * 2 + 8];
                a[mi][3] = *(const uint32_t*)&As[row + 8][kb + lc * 2 + 8];
            }
#pragma unroll
            for (int ni = 0; ni < 4; ni++) {
                int col = wn * 32 + ni * 8 + lr;
                b[ni][0] = *(const uint32_t*)&Bs[col][kb + lc * 2];
                b[ni][1] = *(const uint32_t*)&Bs[col][kb + lc * 2 + 8];
            }
#pragma unroll
            for (int mi = 0; mi < 2; mi++)
#pragma unroll
                for (int ni = 0; ni < 4; ni++) {
                    asm volatile(
                        "mma.sync.aligned.m16n8k16.row.col.f32.f16.f16.f32 "
                        "{%0,%1,%2,%3}, {%4,%5,%6,%7}, {%8,%9}, {%0,%1,%2,%3};"
                        : "+f"(acc[mi][ni][0]), "+f"(acc[mi][ni][1]),
                          "+f"(acc[mi][ni][2]), "+f"(acc[mi][ni][3])
                        : "r"(a[mi][0]), "r"(a[mi][1]), "r"(a[mi][2]), "r"(a[mi][3]),
                          "r"(b[ni][0]), "r"(b[ni][1]));
                }
        }
        __syncthreads();
    }

    float beta = 1.0f, omb = 0.0f;
    if (mode == 1) {
        float sv = *skipPtr;
        beta = 1.0f / (1.0f + expf(-sv));
        omb = 1.0f - beta;
    }

#pragma unroll
    for (int mi = 0; mi < 2; mi++) {
#pragma unroll
        for (int ni = 0; ni < 4; ni++) {
            int row0 = bm + wm * 32 + mi * 16 + lr;
            int col  = bn + wn * 32 + ni * 8 + (lc << 1);
            float b0 = bias[col], b1 = bias[col + 1];
#pragma unroll
            for (int half = 0; half < 2; half++) {
                int row = row0 + half * 8;
                float v0 = acc[mi][ni][half * 2 + 0] + b0;
                float v1 = acc[mi][ni][half * 2 + 1] + b1;
                if (mode == 1) {
                    float2 xo = *(const float2*)(xold + (size_t)row * DMC + col);
                    v0 = beta * v0 + omb * xo.x;
                    v1 = beta * v1 + omb * xo.y;
                }
                if (gelu_after) { v0 = gelu_f(v0); v1 = gelu_f(v1); }
                *(float2*)(C + (size_t)row * ldc + col) = make_float2(v0, v1);
            }
        }
    }
}

// ---------------------------------------------------------------------------
// Fused edge attention + aggregation + GELU (R3 design)
__global__ __launch_bounds__(256)
void agg_kernel(const int* __restrict__ rowptr, const int* __restrict__ col,
                const float* __restrict__ q, const float* __restrict__ kt,
                const float* __restrict__ vt, const float* __restrict__ prel,
                float* __restrict__ agg, int ndst) {
    int gid = blockIdx.x * blockDim.x + threadIdx.x;
    int w = gid >> 5;
    int lane = gid & 31;
    if (w >= ndst * NHC) return;
    int dN = w >> 2;
    int h = w & 3;
    int base = rowptr[dN];
    int deg = rowptr[dN + 1] - base;

    float accx = 0.0f, accy = 0.0f;
    if (deg > 0) {
        const size_t hoff = (size_t)h * NDC + lane * 2;
        float2 qv = *(const float2*)(q + (size_t)dN * LDPROJ + hoff);
        float pr = prel[h] * 0.125f;

        if (deg <= 32) {
            float lg0 = -INFINITY;
            float m = -INFINITY;
            for (int j = 0; j < deg; j++) {
                int s = col[base + j];
                float2 kv = *(const float2*)(kt + (size_t)s * LDPROJ + hoff);
                float p = qv.x * kv.x + qv.y * kv.y;
#pragma unroll
                for (int o = 16; o > 0; o >>= 1) p += __shfl_xor_sync(0xffffffffu, p, o);
                float lg = p * pr;
                if (j == lane) lg0 = lg;
                m = fmaxf(m, lg);
            }
            float e0 = (lane < deg) ? expf(lg0 - m) : 0.0f;
            float tsum = e0;
#pragma unroll
            for (int o = 16; o > 0; o >>= 1) tsum += __shfl_xor_sync(0xffffffffu, tsum, o);
            float inv = 1.0f / (tsum + 1e-16f);
            for (int j = 0; j < deg; j++) {
                float a = __shfl_sync(0xffffffffu, e0, j) * inv;
                int s = col[base + j];
                float2 v = *(const float2*)(vt + (size_t)s * LDPROJ + hoff);
                accx = fmaf(a, v.x, accx);
                accy = fmaf(a, v.y, accy);
            }
        } else {
            float m = -INFINITY;
            for (int j = 0; j < deg; j++) {
                int s = col[base + j];
                float2 kv = *(const float2*)(kt + (size_t)s * LDPROJ + hoff);
                float p = qv.x * kv.x + qv.y * kv.y;
#pragma unroll
                for (int o = 16; o > 0; o >>= 1) p += __shfl_xor_sync(0xffffffffu, p, o);
                m = fmaxf(m, p * pr);
            }
            float ssum = 0.0f;
            for (int j = 0; j < deg; j++) {
                int s = col[base + j];
                float2 kv = *(const float2*)(kt + (size_t)s * LDPROJ + hoff);
                float p = qv.x * kv.x + qv.y * kv.y;
#pragma unroll
                for (int o = 16; o > 0; o >>= 1) p += __shfl_xor_sync(0xffffffffu, p, o);
                ssum += expf(p * pr - m);
            }
            float inv = 1.0f / (ssum + 1e-16f);
            for (int j = 0; j < deg; j++) {
                int s = col[base + j];
                float2 kv = *(const float2*)(kt + (size_t)s * LDPROJ + hoff);
                float p = qv.x * kv.x + qv.y * kv.y;
#pragma unroll
                for (int o = 16; o > 0; o >>= 1) p += __shfl_xor_sync(0xffffffffu, p, o);
                float a = expf(p * pr - m) * inv;
                float2 v = *(const float2*)(vt + (size_t)s * LDPROJ + hoff);
                accx = fmaf(a, v.x, accx);
                accy = fmaf(a, v.y, accy);
            }
        }
    }
    *(float2*)(agg + (size_t)dN * DMC + (size_t)h * NDC + lane * 2) =
        make_float2(gelu_f(accx), gelu_f(accy));
}

// ---------------------------------------------------------------------------
extern "C" void kernel_launch(void* const* d_in, const int* in_sizes, int n_in,
                              void* d_out, int out_size) {
    (void)in_sizes; (void)n_in; (void)out_size;

    float* base = nullptr;
    cudaGetSymbolAddress((void**)&base, g_buf);

    const int*   user_ids  = (const int*)d_in[0];
    const float* x_product = (const float*)d_in[1];
    const int*   edge_src  = (const int*)d_in[2];
    const int*   edge_dst  = (const int*)d_in[3];
    const float* emb       = (const float*)d_in[4];
    const float* Wk        = (const float*)d_in[5];
    const float* bk        = (const float*)d_in[6];
    const float* Wq        = (const float*)d_in[7];
    const float* bq        = (const float*)d_in[8];
    const float* Wv        = (const float*)d_in[9];
    const float* bv        = (const float*)d_in[10];
    const float* Wout      = (const float*)d_in[11];
    const float* bout      = (const float*)d_in[12];
    const float* skipp     = (const float*)d_in[13];
    const float* arel      = (const float*)d_in[14];
    const float* mrel      = (const float*)d_in[15];
    const float* prel      = (const float*)d_in[16];

    float*  xuA   = base + OFF_XUA;
    float*  xuB   = base + OFF_XUB;
    float*  projU = base + OFF_PROJU;
    float*  aggU  = base + OFF_AGGU;
    float*  xpB   = base + OFF_XPB;
    float*  projP = base + OFF_PROJP;
    float*  aggP  = base + OFF_AGGP;
    __half* WbigT = (__half*)(base + OFF_WBIGT);
    float*  bbig  = base + OFF_BBIG;
    __half* WoutT = (__half*)(base + OFF_WOUTT);

    int* ibase   = (int*)(base + OFF_INT);
    int* rowptrP = ibase + I_ROWP;
    int* rowptrU = ibase + I_ROWU;
    int* degP    = ibase + I_DEGP;
    int* degU    = ibase + I_DEGU;
    int* curP    = ibase + I_CURP;
    int* curU    = ibase + I_CURU;
    int* colP    = ibase + I_COLP;
    int* colU    = ibase + I_COLU;

    float* out_xu = (float*)d_out;
    float* out_xp = (float*)d_out + SZ_U;

    // 1. Weight assembly (fp16, transposed)
    copyq_kernel<<<dim3(4, 256), 256>>>(Wq, bq, WbigT, bbig);
    fuse_w_kernel<<<dim3(8, 256), 256>>>(Wk, Wv, arel, mrel, WbigT);
    fuse_b_kernel<<<8, 256>>>(bk, bv, arel, mrel, bbig);
    woutT_kernel<<<dim3(4, 256), 256>>>(Wout, WoutT);

    // 2. Gather user embeddings
    {
        size_t n = (size_t)NUC * (DMC / 4);
        gather_kernel<<<(unsigned)((n + 255) / 256), 256>>>(user_ids, emb, xuA);
    }

    // 3. CSRs (reused across layers)
    cudaMemsetAsync(degP, 0, (size_t)NPC * sizeof(int));
    cudaMemsetAsync(degU, 0, (size_t)NUC * sizeof(int));
    count_deg<<<(NEC + 255) / 256, 256>>>(edge_src, edge_dst, degP, degU);
    scan_kernel<<<1, 1024>>>(degP, rowptrP, curP, NPC);
    scan_kernel<<<1, 1024>>>(degU, rowptrU, curU, NUC);
    build_csr<<<(NEC + 255) / 256, 256>>>(edge_src, edge_dst, curP, curU, colP, colU);

    for (int l = 0; l < 2; l++) {
        const float* xu_in = l ? xuB : xuA;
        const float* xp_in = l ? xpB : x_product;
        float* xu_out = l ? out_xu : xuB;
        float* xp_out = l ? out_xp : xpB;
        int gelu_after = (l == 0) ? 1 : 0;

        // Projections: [M,256] x [768,256]^T
        {
            size_t cu = (size_t)(l * 2 + 0), cp = (size_t)(l * 2 + 1);
            gemm_fp16<<<dim3(LDPROJ / 128, NUC / 64), 256>>>(
                xu_in, WbigT + cu * LDPROJ * DMC, bbig + cu * LDPROJ,
                projU, LDPROJ, 0, nullptr, nullptr, 0);
            gemm_fp16<<<dim3(LDPROJ / 128, NPC / 64), 256>>>(
                xp_in, WbigT + cp * LDPROJ * DMC, bbig + cp * LDPROJ,
                projP, LDPROJ, 0, nullptr, nullptr, 0);
        }

        // rel 0: user -> product
        {
            unsigned blocks = (unsigned)(((size_t)NPC * NHC * 32 + 255) / 256);
            agg_kernel<<<blocks, 256>>>(rowptrP, colP,
                                        projP, projU + DMC, projU + 2 * DMC,
                                        prel + (size_t)(l * 2 + 0) * NHC, aggP, NPC);
        }
        // rel 1: product -> user
        {
            unsigned blocks = (unsigned)(((size_t)NUC * NHC * 32 + 255) / 256);
            agg_kernel<<<blocks, 256>>>(rowptrU, colU,
                                        projU, projP + DMC, projP + 2 * DMC,
                                        prel + (size_t)(l * 2 + 1) * NHC, aggU, NUC);
        }

        // Output GEMMs with skip blend (+ inter-layer gelu for l==0)
        {
            gemm_fp16<<<dim3(DMC / 128, NPC / 64), 256>>>(
                aggP, WoutT + (size_t)(l * 2 + 1) * DMC * DMC, bout + (size_t)(l * 2 + 1) * DMC,
                xp_out, DMC, 1, xp_in, skipp + (l * 2 + 1), gelu_after);
            gemm_fp16<<<dim3(DMC / 128, NUC / 64), 256>>>(
                aggU, WoutT + (size_t)(l * 2 + 0) * DMC * DMC, bout + (size_t)(l * 2 + 0) * DMC,
                xu_out, DMC, 1, xu_in, skipp + (l * 2 + 0), gelu_after);
        }
    }
}